// round 1
// baseline (speedup 1.0000x reference)
#include <cuda_runtime.h>
#include <stdint.h>

// out[b,c, pr*64+i, pc*64+j] = x[b,c, qr*64+i, qc*64+j] + pos[c*64+q]
//   p = pr*8+pc, q = (p+c) & 63
// B=8, C=64, H=W=512. Pure streaming permutation: 1 GiB HBM traffic.
//
// Vectorized float4: each output row segment of 64 floats maps to a contiguous
// 64-float source segment, so 16B loads/stores stay aligned and coalesced.

#define B_ 8
#define C_ 64
#define HW_ 512
// float4 elements per image row
#define W4_ 128u

__global__ __launch_bounds__(256) void crosspatch_kernel(
    const float4* __restrict__ x4,
    const float* __restrict__ pos,
    float4* __restrict__ out4)
{
    // Each thread: one float4 of output. Total = 8*64*512*512/4 = 33,554,432.
    uint32_t idx = blockIdx.x * 256u + threadIdx.x;

    // decode output coordinates
    uint32_t w4 = idx & (W4_ - 1u);          // float4 column within row
    uint32_t t  = idx >> 7;                  // / 128
    uint32_t h  = t & (HW_ - 1u);            // row within image
    uint32_t bc = t >> 9;                    // image index b*64+c
    uint32_t c  = bc & 63u;

    uint32_t w  = w4 << 2;                   // float column
    uint32_t pc = w >> 6;                    // output patch col
    uint32_t j4 = w4 & 15u;                  // float4 col within 64-float block
    uint32_t pr = h >> 6;                    // output patch row
    uint32_t i  = h & 63u;                   // row within patch

    uint32_t p = pr * 8u + pc;
    uint32_t q = (p + c) & 63u;
    uint32_t qr = q >> 3;
    uint32_t qc = q & 7u;

    // source float4 index: ((bc*512 + qr*64 + i) * 512 + qc*64 + j) / 4
    uint32_t src = (bc << 16) * 2u            /* bc * 512*512/4 = bc*65536 ... */;
    // careful: bc*512*512/4 = bc * 65536
    src = bc * 65536u + (qr * 64u + i) * W4_ + qc * 16u + j4;

    float bias = __ldg(&pos[c * 64u + q]);

    float4 v = x4[src];
    v.x += bias; v.y += bias; v.z += bias; v.w += bias;
    out4[idx] = v;
}

extern "C" void kernel_launch(void* const* d_in, const int* in_sizes, int n_in,
                              void* d_out, int out_size)
{
    const float4* x4  = (const float4*)d_in[0];
    const float*  pos = (const float*)d_in[1];
    float4* out4 = (float4*)d_out;

    // total float4 outputs = 8*64*512*512/4 = 33,554,432 -> 131072 blocks of 256
    uint32_t n4 = (uint32_t)((size_t)8 * 64 * 512 * 512 / 4);
    crosspatch_kernel<<<n4 / 256u, 256u>>>(x4, pos, out4);
}

// round 2
// speedup vs baseline: 1.0417x; 1.0417x over previous
#include <cuda_runtime.h>
#include <stdint.h>

// out[b,c, pr*64+i, pc*64+j] = x[b,c, qr*64+i, qc*64+j] + pos[c*64+q]
//   p = pr*8+pc, q = (p+c) & 63
// B=8, C=64, H=W=512. 1 GiB HBM traffic; pure streaming permutation.
//
// R2: 4 float4 per thread (front-batched loads, MLP_p1=4) + streaming
// cache hints (__ldcs/__stcs). Each of the 4 chunks is warp-coalesced.

#define W4_ 128u   // float4 per image row

__global__ __launch_bounds__(256) void crosspatch_kernel(
    const float4* __restrict__ x4,
    const float* __restrict__ pos,
    float4* __restrict__ out4)
{
    const uint32_t base = blockIdx.x * 1024u + threadIdx.x;

    uint32_t srcs[4];
    float    biases[4];
    uint32_t dsts[4];

    #pragma unroll
    for (int k = 0; k < 4; k++) {
        uint32_t idx = base + (uint32_t)k * 256u;
        dsts[k] = idx;

        // decode output coordinates
        uint32_t w4 = idx & (W4_ - 1u);      // float4 column within row
        uint32_t t  = idx >> 7;
        uint32_t h  = t & 511u;              // row within image
        uint32_t bc = t >> 9;                // b*64 + c
        uint32_t c  = bc & 63u;

        uint32_t pc = w4 >> 4;               // output patch col (w4/16)
        uint32_t j4 = w4 & 15u;              // float4 within 64-float block
        uint32_t pr = h >> 6;                // output patch row
        uint32_t i  = h & 63u;

        uint32_t p = pr * 8u + pc;
        uint32_t q = (p + c) & 63u;
        uint32_t qr = q >> 3;
        uint32_t qc = q & 7u;

        srcs[k]   = bc * 65536u + (qr * 64u + i) * W4_ + qc * 16u + j4;
        biases[k] = __ldg(&pos[c * 64u + q]);
    }

    // front-batched independent loads
    float4 v[4];
    #pragma unroll
    for (int k = 0; k < 4; k++) v[k] = __ldcs(&x4[srcs[k]]);

    #pragma unroll
    for (int k = 0; k < 4; k++) {
        float b = biases[k];
        v[k].x += b; v[k].y += b; v[k].z += b; v[k].w += b;
        __stcs(&out4[dsts[k]], v[k]);
    }
}

extern "C" void kernel_launch(void* const* d_in, const int* in_sizes, int n_in,
                              void* d_out, int out_size)
{
    const float4* x4  = (const float4*)d_in[0];
    const float*  pos = (const float*)d_in[1];
    float4* out4 = (float4*)d_out;

    // total float4 outputs = 8*64*512*512/4 = 33,554,432
    // 4 per thread, 256 threads/block -> 32768 blocks
    uint32_t n4 = (uint32_t)((size_t)8 * 64 * 512 * 512 / 4);
    crosspatch_kernel<<<n4 / 1024u, 256u>>>(x4, pos, out4);
}

// round 3
// speedup vs baseline: 1.0423x; 1.0006x over previous
#include <cuda_runtime.h>
#include <stdint.h>

// out[b,c, pr*64+i, pc*64+j] = x[b,c, qr*64+i, qc*64+j] + pos[c*64+q]
//   p = pr*8+pc, q = (p+c) & 63
// B=8, C=64, H=W=512. 1 GiB HBM traffic; pure streaming permutation.
//
// R3: 8 float4 per thread (front-batched loads, MLP_p1=8) + streaming
// cache hints. Each of the 8 chunks is warp-coalesced (stride 256 threads).

#define W4_ 128u   // float4 per image row
#define ILP 8

__global__ __launch_bounds__(256) void crosspatch_kernel(
    const float4* __restrict__ x4,
    const float* __restrict__ pos,
    float4* __restrict__ out4)
{
    const uint32_t base = blockIdx.x * (256u * ILP) + threadIdx.x;

    uint32_t srcs[ILP];
    float    biases[ILP];

    #pragma unroll
    for (int k = 0; k < ILP; k++) {
        uint32_t idx = base + (uint32_t)k * 256u;

        // decode output coordinates
        uint32_t w4 = idx & (W4_ - 1u);      // float4 column within row
        uint32_t t  = idx >> 7;
        uint32_t h  = t & 511u;              // row within image
        uint32_t bc = t >> 9;                // b*64 + c
        uint32_t c  = bc & 63u;

        uint32_t pc = w4 >> 4;               // output patch col (w4/16)
        uint32_t j4 = w4 & 15u;              // float4 within 64-float block
        uint32_t pr = h >> 6;                // output patch row
        uint32_t i  = h & 63u;

        uint32_t p = pr * 8u + pc;
        uint32_t q = (p + c) & 63u;
        uint32_t qr = q >> 3;
        uint32_t qc = q & 7u;

        srcs[k]   = bc * 65536u + (qr * 64u + i) * W4_ + qc * 16u + j4;
        biases[k] = __ldg(&pos[c * 64u + q]);
    }

    // front-batched independent loads (8 outstanding LDG.128 per thread)
    float4 v[ILP];
    #pragma unroll
    for (int k = 0; k < ILP; k++) v[k] = __ldcs(&x4[srcs[k]]);

    #pragma unroll
    for (int k = 0; k < ILP; k++) {
        float b = biases[k];
        v[k].x += b; v[k].y += b; v[k].z += b; v[k].w += b;
        __stcs(&out4[base + (uint32_t)k * 256u], v[k]);
    }
}

extern "C" void kernel_launch(void* const* d_in, const int* in_sizes, int n_in,
                              void* d_out, int out_size)
{
    const float4* x4  = (const float4*)d_in[0];
    const float*  pos = (const float*)d_in[1];
    float4* out4 = (float4*)d_out;

    // total float4 outputs = 8*64*512*512/4 = 33,554,432
    // 8 per thread, 256 threads/block -> 16384 blocks
    uint32_t n4 = (uint32_t)((size_t)8 * 64 * 512 * 512 / 4);
    crosspatch_kernel<<<n4 / (256u * ILP), 256u>>>(x4, pos, out4);
}

// round 4
// speedup vs baseline: 1.0432x; 1.0008x over previous
#include <cuda_runtime.h>
#include <stdint.h>

// out[b,c, pr*64+i, pc*64+j] = x[b,c, qr*64+i, qc*64+j] + pos[c*64+q]
//   p = pr*8+pc, q = (p+c) & 63
// B=8, C=64, H=W=512. 1 GiB HBM traffic; pure streaming permutation.
//
// R4: 256-bit global accesses (ld/st.global.v8.f32, sm_100+), 4 per thread.
// Warp presents 1024B contiguous per instruction on both sides.
// Permutation granularity is 256B, so all v8 accesses are 32B-aligned.

#define ILP 4

__device__ __forceinline__ void ldg_v8_cs(const float* p, float* v) {
    asm volatile(
        "ld.global.cs.v8.f32 {%0,%1,%2,%3,%4,%5,%6,%7}, [%8];"
        : "=f"(v[0]), "=f"(v[1]), "=f"(v[2]), "=f"(v[3]),
          "=f"(v[4]), "=f"(v[5]), "=f"(v[6]), "=f"(v[7])
        : "l"(p));
}

__device__ __forceinline__ void stg_v8_cs(float* p, const float* v) {
    asm volatile(
        "st.global.cs.v8.f32 [%0], {%1,%2,%3,%4,%5,%6,%7,%8};"
        :: "l"(p),
           "f"(v[0]), "f"(v[1]), "f"(v[2]), "f"(v[3]),
           "f"(v[4]), "f"(v[5]), "f"(v[6]), "f"(v[7])
        : "memory");
}

__global__ __launch_bounds__(256) void crosspatch_kernel(
    const float* __restrict__ x,
    const float* __restrict__ pos,
    float* __restrict__ out)
{
    // idx in units of 8 floats (32B). Per image row: 64 v8 units.
    const uint32_t base = blockIdx.x * (256u * ILP) + threadIdx.x;

    uint32_t srcs[ILP];   // in v8 units
    float    biases[ILP];

    #pragma unroll
    for (int k = 0; k < ILP; k++) {
        uint32_t idx = base + (uint32_t)k * 256u;

        uint32_t w8 = idx & 63u;             // v8 column within row
        uint32_t t  = idx >> 6;
        uint32_t h  = t & 511u;              // row within image
        uint32_t bc = t >> 9;                // b*64 + c
        uint32_t c  = bc & 63u;

        uint32_t pc = w8 >> 3;               // output patch col (8 v8 per block)
        uint32_t j8 = w8 & 7u;               // v8 within 64-float block
        uint32_t pr = h >> 6;                // output patch row
        uint32_t i  = h & 63u;

        uint32_t p = pr * 8u + pc;
        uint32_t q = (p + c) & 63u;
        uint32_t qr = q >> 3;
        uint32_t qc = q & 7u;

        // source v8 index: bc*512*512/8 + (qr*64+i)*64 + qc*8 + j8
        srcs[k]   = bc * 32768u + (qr * 64u + i) * 64u + qc * 8u + j8;
        biases[k] = __ldg(&pos[c * 64u + q]);
    }

    // front-batched independent 256-bit loads
    float v[ILP][8];
    #pragma unroll
    for (int k = 0; k < ILP; k++)
        ldg_v8_cs(x + (size_t)srcs[k] * 8u, v[k]);

    #pragma unroll
    for (int k = 0; k < ILP; k++) {
        float b = biases[k];
        #pragma unroll
        for (int e = 0; e < 8; e++) v[k][e] += b;
        stg_v8_cs(out + (size_t)(base + (uint32_t)k * 256u) * 8u, v[k]);
    }
}

extern "C" void kernel_launch(void* const* d_in, const int* in_sizes, int n_in,
                              void* d_out, int out_size)
{
    const float* x   = (const float*)d_in[0];
    const float* pos = (const float*)d_in[1];
    float* out = (float*)d_out;

    // total v8 outputs = 8*64*512*512/8 = 16,777,216
    // 4 per thread, 256 threads/block -> 16384 blocks
    uint32_t n8 = (uint32_t)((size_t)8 * 64 * 512 * 512 / 8);
    crosspatch_kernel<<<n8 / (256u * ILP), 256u>>>(x, pos, out);
}